// round 1
// baseline (speedup 1.0000x reference)
#include <cuda_runtime.h>
#include <math.h>

#define T_DIM 2048
#define D_DIM 2048
#define H_NUM 32
#define HD_DIM 64

// Scratch (allocation-free rule: __device__ globals)
__device__ float g_Q[H_NUM * T_DIM * HD_DIM];   // [H][T][64], RoPE'd in place
__device__ float g_K[H_NUM * T_DIM * HD_DIM];
__device__ float g_V[H_NUM * T_DIM * HD_DIM];
__device__ float g_O[T_DIM * D_DIM];            // attention output, [T][D]

// head -> module index, HEAD_COUNTS = {8,6,4,4,6,4}
__constant__ int c_h2m[H_NUM] = {0,0,0,0,0,0,0,0,
                                 1,1,1,1,1,1,
                                 2,2,2,2,
                                 3,3,3,3,
                                 4,4,4,4,4,4,
                                 5,5,5,5};

// ---------------------------------------------------------------------------
// C = A * W^T.  A:[2048,2048] row-major, W:[2048,2048] row-major (both K-contig).
// BM=BN=64, BK=16, 256 threads, 4x4 microtile. Smem tiles stored K-major
// (As[kk][m]) so the inner loop is two LDS.128 + 16 FFMA.
// HEAD_LAYOUT: write C[t][o] to [(o>>6)*T + t]*64 + (o&63)  (per-head layout).
// ---------------------------------------------------------------------------
template<bool HEAD_LAYOUT>
__global__ __launch_bounds__(256, 4) void gemm_nt_kernel(
    const float* __restrict__ A, const float* __restrict__ W, float* __restrict__ C)
{
    __shared__ float As[16][68];
    __shared__ float Bs[16][68];

    const int tid = threadIdx.x;
    const int tx = tid & 15, ty = tid >> 4;
    const int t0 = blockIdx.x * 64, o0 = blockIdx.y * 64;
    const int lrow = tid >> 2;          // 0..63
    const int lcol = (tid & 3) << 2;    // 0,4,8,12

    float acc[4][4];
#pragma unroll
    for (int i = 0; i < 4; i++)
#pragma unroll
        for (int j = 0; j < 4; j++) acc[i][j] = 0.f;

    const float* Aptr = A + (size_t)(t0 + lrow) * D_DIM + lcol;
    const float* Wptr = W + (size_t)(o0 + lrow) * D_DIM + lcol;

    for (int k0 = 0; k0 < D_DIM; k0 += 16) {
        float4 a = *(const float4*)(Aptr + k0);
        float4 b = *(const float4*)(Wptr + k0);
        __syncthreads();
        As[lcol + 0][lrow] = a.x; As[lcol + 1][lrow] = a.y;
        As[lcol + 2][lrow] = a.z; As[lcol + 3][lrow] = a.w;
        Bs[lcol + 0][lrow] = b.x; Bs[lcol + 1][lrow] = b.y;
        Bs[lcol + 2][lrow] = b.z; Bs[lcol + 3][lrow] = b.w;
        __syncthreads();
#pragma unroll
        for (int kk = 0; kk < 16; kk++) {
            float4 av = *(const float4*)&As[kk][ty << 2];
            float4 bv = *(const float4*)&Bs[kk][tx << 2];
            acc[0][0] += av.x * bv.x; acc[0][1] += av.x * bv.y;
            acc[0][2] += av.x * bv.z; acc[0][3] += av.x * bv.w;
            acc[1][0] += av.y * bv.x; acc[1][1] += av.y * bv.y;
            acc[1][2] += av.y * bv.z; acc[1][3] += av.y * bv.w;
            acc[2][0] += av.z * bv.x; acc[2][1] += av.z * bv.y;
            acc[2][2] += av.z * bv.z; acc[2][3] += av.z * bv.w;
            acc[3][0] += av.w * bv.x; acc[3][1] += av.w * bv.y;
            acc[3][2] += av.w * bv.z; acc[3][3] += av.w * bv.w;
        }
    }

#pragma unroll
    for (int i = 0; i < 4; i++) {
        int t = t0 + (ty << 2) + i;
        float4 v = make_float4(acc[i][0], acc[i][1], acc[i][2], acc[i][3]);
        if (HEAD_LAYOUT) {
            int h = o0 >> 6;  // BN=64 == HD, so the whole block is one head
            *(float4*)&C[((size_t)h * T_DIM + t) * HD_DIM + (tx << 2)] = v;
        } else {
            *(float4*)&C[(size_t)t * D_DIM + o0 + (tx << 2)] = v;
        }
    }
}

// ---------------------------------------------------------------------------
// RoPE, in place on g_Q / g_K.  One thread per (h, t, i<32) pair.
// out[i]    = x[i]*cos(t*f_i) - x[i+32]*sin(t*f_i)
// out[i+32] = x[i+32]*cos(t*f_i) + x[i]*sin(t*f_i),  f_i = 10000^(-i/32)
// ---------------------------------------------------------------------------
__global__ __launch_bounds__(256) void rope_kernel()
{
    int idx = blockIdx.x * 256 + threadIdx.x;   // 0 .. H*T*32-1 = 2^21-1
    int i = idx & 31;
    int t = (idx >> 5) & (T_DIM - 1);
    int h = idx >> 16;

    // log2(10000)/32 = 0.4152410118609203
    float f = exp2f(-(float)i * 0.41524101186092030f);
    float ang = (float)t * f;
    float c = cosf(ang), s = sinf(ang);

    size_t base = ((size_t)h * T_DIM + t) * HD_DIM + i;
    float q1 = g_Q[base], q2 = g_Q[base + 32];
    g_Q[base]      = q1 * c - q2 * s;
    g_Q[base + 32] = q2 * c + q1 * s;
    float k1 = g_K[base], k2 = g_K[base + 32];
    g_K[base]      = k1 * c - k2 * s;
    g_K[base + 32] = k2 * c + k1 * s;
}

// ---------------------------------------------------------------------------
// Flash-style causal attention per (64-query tile, head).
// s = (q.k * 0.125 * temp[h] + bias[q][k]) * w[h];  masked -> -1e30 (exp==0,
// matching (NEG+bias)*w which also underflows).  KP buffer holds the K tile
// (transposed [hd][k]) during S, then P^T ([k][r]) during PV -> 48KB smem.
// ---------------------------------------------------------------------------
__global__ __launch_bounds__(256) void attn_kernel(
    const float* __restrict__ bias, const float* __restrict__ modw,
    const float* __restrict__ temps)
{
    __shared__ float Qs[64 * 64];   // [hd][r]
    __shared__ float KP[64 * 64];   // K: [hd][k]  then  P^T: [k][r]
    __shared__ float Vs[64 * 64];   // [k][hd]

    const int tid = threadIdx.x;
    const int tx = tid & 15, ty = tid >> 4;
    const int qb = gridDim.x - 1 - blockIdx.x;   // heaviest tiles first
    const int h  = blockIdx.y;
    const int q0 = qb * 64;

    const float sc  = 0.125f * temps[h];
    const float wgt = modw[c_h2m[h]];

    const float* Qg = g_Q + ((size_t)h * T_DIM + q0) * HD_DIM;
    const float* Kg = g_K + (size_t)h * T_DIM * HD_DIM;
    const float* Vg = g_V + (size_t)h * T_DIM * HD_DIM;

    const int lr = tid >> 4;          // 0..15
    const int lc = (tid & 15) << 2;   // 0..60

    // Load Q tile transposed into Qs[hd][r]
#pragma unroll
    for (int it = 0; it < 4; it++) {
        int r = lr + it * 16;
        float4 v = *(const float4*)&Qg[r * HD_DIM + lc];
        Qs[(lc + 0) * 64 + r] = v.x; Qs[(lc + 1) * 64 + r] = v.y;
        Qs[(lc + 2) * 64 + r] = v.z; Qs[(lc + 3) * 64 + r] = v.w;
    }

    float m[4], l[4], o[4][4];
#pragma unroll
    for (int i = 0; i < 4; i++) {
        m[i] = -INFINITY; l[i] = 0.f;
#pragma unroll
        for (int j = 0; j < 4; j++) o[i][j] = 0.f;
    }

    for (int kb = 0; kb <= qb; kb++) {
        const int k0 = kb * 64;
        __syncthreads();   // previous iteration done with KP / Vs
#pragma unroll
        for (int it = 0; it < 4; it++) {
            int r = lr + it * 16;
            float4 kv = *(const float4*)&Kg[(size_t)(k0 + r) * HD_DIM + lc];
            KP[(lc + 0) * 64 + r] = kv.x; KP[(lc + 1) * 64 + r] = kv.y;
            KP[(lc + 2) * 64 + r] = kv.z; KP[(lc + 3) * 64 + r] = kv.w;
            float4 vv = *(const float4*)&Vg[(size_t)(k0 + r) * HD_DIM + lc];
            *(float4*)&Vs[r * 64 + lc] = vv;
        }
        __syncthreads();

        // S = Q K^T  (64x64x64)
        float s[4][4];
#pragma unroll
        for (int i = 0; i < 4; i++)
#pragma unroll
            for (int j = 0; j < 4; j++) s[i][j] = 0.f;
#pragma unroll 8
        for (int hd = 0; hd < 64; hd++) {
            float4 qv = *(const float4*)&Qs[hd * 64 + (ty << 2)];
            float4 kv = *(const float4*)&KP[hd * 64 + (tx << 2)];
            s[0][0] += qv.x * kv.x; s[0][1] += qv.x * kv.y;
            s[0][2] += qv.x * kv.z; s[0][3] += qv.x * kv.w;
            s[1][0] += qv.y * kv.x; s[1][1] += qv.y * kv.y;
            s[1][2] += qv.y * kv.z; s[1][3] += qv.y * kv.w;
            s[2][0] += qv.z * kv.x; s[2][1] += qv.z * kv.y;
            s[2][2] += qv.z * kv.z; s[2][3] += qv.z * kv.w;
            s[3][0] += qv.w * kv.x; s[3][1] += qv.w * kv.y;
            s[3][2] += qv.w * kv.z; s[3][3] += qv.w * kv.w;
        }

        // scale + bias + module weight + causal mask
#pragma unroll
        for (int i = 0; i < 4; i++) {
            int q = q0 + (ty << 2) + i;
            float4 bv = *(const float4*)&bias[(size_t)q * T_DIM + k0 + (tx << 2)];
            float bb[4] = {bv.x, bv.y, bv.z, bv.w};
#pragma unroll
            for (int j = 0; j < 4; j++) {
                int k = k0 + (tx << 2) + j;
                float v = (s[i][j] * sc + bb[j]) * wgt;
                s[i][j] = (k > q) ? -1e30f : v;
            }
        }

        // online softmax
        float p[4][4], alpha[4];
#pragma unroll
        for (int i = 0; i < 4; i++) {
            float rm = fmaxf(fmaxf(s[i][0], s[i][1]), fmaxf(s[i][2], s[i][3]));
#pragma unroll
            for (int off = 8; off >= 1; off >>= 1)
                rm = fmaxf(rm, __shfl_xor_sync(0xffffffffu, rm, off));
            float mn = fmaxf(m[i], rm);
            alpha[i] = expf(m[i] - mn);
            m[i] = mn;
            float rs = 0.f;
#pragma unroll
            for (int j = 0; j < 4; j++) { p[i][j] = expf(s[i][j] - mn); rs += p[i][j]; }
#pragma unroll
            for (int off = 8; off >= 1; off >>= 1)
                rs += __shfl_xor_sync(0xffffffffu, rs, off);
            l[i] = l[i] * alpha[i] + rs;
#pragma unroll
            for (int j = 0; j < 4; j++) o[i][j] *= alpha[i];
        }

        __syncthreads();   // everyone done reading K from KP
        // store P^T into KP: KP[k][r]
#pragma unroll
        for (int j = 0; j < 4; j++) {
            float4 pv = make_float4(p[0][j], p[1][j], p[2][j], p[3][j]);
            *(float4*)&KP[((tx << 2) + j) * 64 + (ty << 2)] = pv;
        }
        __syncthreads();

        // O += P V  (64x64x64)
#pragma unroll 8
        for (int kk = 0; kk < 64; kk++) {
            float4 pv = *(const float4*)&KP[kk * 64 + (ty << 2)];
            float4 vv = *(const float4*)&Vs[kk * 64 + (tx << 2)];
            o[0][0] += pv.x * vv.x; o[0][1] += pv.x * vv.y;
            o[0][2] += pv.x * vv.z; o[0][3] += pv.x * vv.w;
            o[1][0] += pv.y * vv.x; o[1][1] += pv.y * vv.y;
            o[1][2] += pv.y * vv.z; o[1][3] += pv.y * vv.w;
            o[2][0] += pv.z * vv.x; o[2][1] += pv.z * vv.y;
            o[2][2] += pv.z * vv.z; o[2][3] += pv.z * vv.w;
            o[3][0] += pv.w * vv.x; o[3][1] += pv.w * vv.y;
            o[3][2] += pv.w * vv.z; o[3][3] += pv.w * vv.w;
        }
    }

    // normalize + write to [T][D] buffer for the output projection
#pragma unroll
    for (int i = 0; i < 4; i++) {
        int q = q0 + (ty << 2) + i;
        float inv = 1.f / l[i];
        float4 v = make_float4(o[i][0] * inv, o[i][1] * inv,
                               o[i][2] * inv, o[i][3] * inv);
        *(float4*)&g_O[(size_t)q * D_DIM + h * HD_DIM + (tx << 2)] = v;
    }
}

// ---------------------------------------------------------------------------
extern "C" void kernel_launch(void* const* d_in, const int* in_sizes, int n_in,
                              void* d_out, int out_size)
{
    const float* x  = (const float*)d_in[0];
    // d_in[1] = causal mask (known tril, handled analytically)
    const float* cb = (const float*)d_in[2];   // context_bias [1,T,T]
    const float* mw = (const float*)d_in[3];   // mod_weights [1,6]
    const float* Wq = (const float*)d_in[4];
    const float* Wk = (const float*)d_in[5];
    const float* Wv = (const float*)d_in[6];
    const float* Wo = (const float*)d_in[7];
    const float* ts = (const float*)d_in[8];   // temp_scales [32]
    float* out = (float*)d_out;

    float *gQ, *gK, *gV, *gO;
    cudaGetSymbolAddress((void**)&gQ, g_Q);
    cudaGetSymbolAddress((void**)&gK, g_K);
    cudaGetSymbolAddress((void**)&gV, g_V);
    cudaGetSymbolAddress((void**)&gO, g_O);

    dim3 grid(T_DIM / 64, D_DIM / 64);   // (32, 32)

    gemm_nt_kernel<true ><<<grid, 256>>>(x, Wq, gQ);
    gemm_nt_kernel<true ><<<grid, 256>>>(x, Wk, gK);
    gemm_nt_kernel<true ><<<grid, 256>>>(x, Wv, gV);

    rope_kernel<<<(H_NUM * T_DIM * 32) / 256, 256>>>();

    attn_kernel<<<dim3(T_DIM / 64, H_NUM), 256>>>(cb, mw, ts);

    gemm_nt_kernel<false><<<grid, 256>>>(gO, Wo, out);
}

// round 3
// speedup vs baseline: 1.6353x; 1.6353x over previous
#include <cuda_runtime.h>
#include <cuda_bf16.h>
#include <math.h>
#include <stdint.h>

#define T_DIM 2048
#define D_DIM 2048
#define H_NUM 32
#define HD_DIM 64

// ---------------------------------------------------------------------------
// Scratch (__device__ globals; allocation-free rule)
// ---------------------------------------------------------------------------
__device__ float g_Q[H_NUM * T_DIM * HD_DIM];   // [H][T][64], RoPE'd in place
__device__ float g_K[H_NUM * T_DIM * HD_DIM];
__device__ float g_V[H_NUM * T_DIM * HD_DIM];
__device__ float g_O[T_DIM * D_DIM];            // attention output, [T][D]

// bf16 hi/lo splits for tensor-core GEMMs
__device__ __nv_bfloat16 g_xh[D_DIM * D_DIM],  g_xl[D_DIM * D_DIM];
__device__ __nv_bfloat16 g_wqh[D_DIM * D_DIM], g_wql[D_DIM * D_DIM];
__device__ __nv_bfloat16 g_wkh[D_DIM * D_DIM], g_wkl[D_DIM * D_DIM];
__device__ __nv_bfloat16 g_wvh[D_DIM * D_DIM], g_wvl[D_DIM * D_DIM];
__device__ __nv_bfloat16 g_woh[D_DIM * D_DIM], g_wol[D_DIM * D_DIM];
__device__ __nv_bfloat16 g_oh[D_DIM * D_DIM],  g_ol[D_DIM * D_DIM];

// head -> module index, HEAD_COUNTS = {8,6,4,4,6,4}
__constant__ int c_h2m[H_NUM] = {0,0,0,0,0,0,0,0,
                                 1,1,1,1,1,1,
                                 2,2,2,2,
                                 3,3,3,3,
                                 4,4,4,4,4,4,
                                 5,5,5,5};

// ---------------------------------------------------------------------------
// PTX helpers (sm_100-safe: cp.async / ldmatrix / mma.sync)
// ---------------------------------------------------------------------------
__device__ __forceinline__ uint32_t s2u(const void* p) {
    uint32_t a;
    asm("{ .reg .u64 t; cvta.to.shared.u64 t, %1; cvt.u32.u64 %0, t; }"
        : "=r"(a) : "l"(p));
    return a;
}
__device__ __forceinline__ void cp16(uint32_t d, const void* s) {
    asm volatile("cp.async.cg.shared.global [%0], [%1], 16;" :: "r"(d), "l"(s));
}
__device__ __forceinline__ void cp_commit() {
    asm volatile("cp.async.commit_group;" ::: "memory");
}
__device__ __forceinline__ void cp_wait1() {
    asm volatile("cp.async.wait_group 1;" ::: "memory");
}
__device__ __forceinline__ void ldm_x4(uint32_t* r, uint32_t a) {
    asm volatile("ldmatrix.sync.aligned.m8n8.x4.shared.b16 {%0,%1,%2,%3}, [%4];"
                 : "=r"(r[0]), "=r"(r[1]), "=r"(r[2]), "=r"(r[3]) : "r"(a));
}
__device__ __forceinline__ void mma16816(float* d, const uint32_t* a,
                                         uint32_t b0, uint32_t b1) {
    asm volatile("mma.sync.aligned.m16n8k16.row.col.f32.bf16.bf16.f32 "
        "{%0,%1,%2,%3},{%4,%5,%6,%7},{%8,%9},{%0,%1,%2,%3};"
        : "+f"(d[0]), "+f"(d[1]), "+f"(d[2]), "+f"(d[3])
        : "r"(a[0]), "r"(a[1]), "r"(a[2]), "r"(a[3]), "r"(b0), "r"(b1));
}

// ---------------------------------------------------------------------------
// fp32 -> bf16 hi/lo split
// ---------------------------------------------------------------------------
__global__ __launch_bounds__(256) void split_kernel(
    const float4* __restrict__ src,
    __nv_bfloat162* __restrict__ hi, __nv_bfloat162* __restrict__ lo)
{
    int i = blockIdx.x * 256 + threadIdx.x;
    float4 v = src[i];
    __nv_bfloat16 h0 = __float2bfloat16(v.x), h1 = __float2bfloat16(v.y);
    __nv_bfloat16 h2 = __float2bfloat16(v.z), h3 = __float2bfloat16(v.w);
    float l0 = v.x - __bfloat162float(h0), l1 = v.y - __bfloat162float(h1);
    float l2 = v.z - __bfloat162float(h2), l3 = v.w - __bfloat162float(h3);
    hi[2 * i]     = __halves2bfloat162(h0, h1);
    hi[2 * i + 1] = __halves2bfloat162(h2, h3);
    lo[2 * i]     = __halves2bfloat162(__float2bfloat16(l0), __float2bfloat16(l1));
    lo[2 * i + 1] = __halves2bfloat162(__float2bfloat16(l2), __float2bfloat16(l3));
}

// ---------------------------------------------------------------------------
// C = A * W^T via mma.sync bf16 hi/lo (3 passes: AhBh + AhBl + AlBh).
// CTA 128x128, 8 warps (2x4) each 64x32, BK=32, 3-stage cp.async pipeline.
// Smem rows padded to 80B for conflict-free ldmatrix.
// ---------------------------------------------------------------------------
#define ROWB      80            // padded row stride in bytes (32 bf16 + 8 pad)
#define ARR_BYTES (128 * ROWB)  // 10240
#define STG_BYTES (4 * ARR_BYTES)
#define N_STAGE   3
#define GEMM_SMEM (N_STAGE * STG_BYTES)

__device__ __forceinline__ void g_load_stage(
    uint32_t st, const __nv_bfloat16* __restrict__ Ah, const __nv_bfloat16* __restrict__ Al,
    const __nv_bfloat16* __restrict__ Bh, const __nv_bfloat16* __restrict__ Bl,
    int t0, int o0, int k0, int tid)
{
    const int r = tid >> 2;             // 0..63 (two rows per array half below)
    const int c = (tid & 3);            // 16B chunk
    const int e = c * 8;                // element offset
    // 8 chunks/thread: 2 per array
#pragma unroll
    for (int half = 0; half < 2; half++) {
        int row = r + half * 64;
        uint32_t so = row * ROWB + c * 16;
        size_t ga = (size_t)(t0 + row) * D_DIM + k0 + e;
        size_t gb = (size_t)(o0 + row) * D_DIM + k0 + e;
        cp16(st + so,                 Ah + ga);
        cp16(st + ARR_BYTES + so,     Al + ga);
        cp16(st + 2 * ARR_BYTES + so, Bh + gb);
        cp16(st + 3 * ARR_BYTES + so, Bl + gb);
    }
    cp_commit();
}

template<bool HEAD_LAYOUT>
__global__ __launch_bounds__(256, 1) void gemm_tc_kernel(
    const __nv_bfloat16* __restrict__ Ah, const __nv_bfloat16* __restrict__ Al,
    const __nv_bfloat16* __restrict__ Bh, const __nv_bfloat16* __restrict__ Bl,
    float* __restrict__ C)
{
    extern __shared__ char smem[];
    const uint32_t sb = s2u(smem);
    const int tid  = threadIdx.x;
    const int w    = tid >> 5;
    const int lane = tid & 31;
    const int t0 = blockIdx.x * 128;
    const int o0 = blockIdx.y * 128;
    const int wm0 = (w >> 2) * 64;      // warp M offset (0 / 64)
    const int wn0 = (w & 3) * 32;       // warp N offset

    float acc[4][4][4];
#pragma unroll
    for (int i = 0; i < 4; i++)
#pragma unroll
        for (int j = 0; j < 4; j++)
#pragma unroll
            for (int q = 0; q < 4; q++) acc[i][j][q] = 0.f;

    g_load_stage(sb,             Ah, Al, Bh, Bl, t0, o0, 0,  tid);
    g_load_stage(sb + STG_BYTES, Ah, Al, Bh, Bl, t0, o0, 32, tid);

    const int lm = lane & 15;
    const uint32_t kb = (uint32_t)(lane >> 4) * 16;

    for (int it = 0; it < 64; it++) {
        cp_wait1();
        __syncthreads();
        if (it < 62)
            g_load_stage(sb + (uint32_t)((it + 2) % N_STAGE) * STG_BYTES,
                         Ah, Al, Bh, Bl, t0, o0, (it + 2) * 32, tid);
        else
            cp_commit();   // empty group keeps wait_group 1 semantics aligned

        const uint32_t st = sb + (uint32_t)(it % N_STAGE) * STG_BYTES;
        const uint32_t aA = st + (uint32_t)(wm0 + lm) * ROWB + kb;
        const uint32_t aB = st + 2u * ARR_BYTES + (uint32_t)(wn0 + lm) * ROWB + kb;

#pragma unroll
        for (int ks = 0; ks < 2; ks++) {
            const uint32_t ko = (uint32_t)ks * 32;
            uint32_t ah[4][4], al[4][4], bh[2][4], bl[2][4];
#pragma unroll
            for (int i = 0; i < 4; i++) {
                ldm_x4(ah[i], aA + (uint32_t)(i * 16) * ROWB + ko);
                ldm_x4(al[i], aA + ARR_BYTES + (uint32_t)(i * 16) * ROWB + ko);
            }
#pragma unroll
            for (int j = 0; j < 2; j++) {
                ldm_x4(bh[j], aB + (uint32_t)(j * 16) * ROWB + ko);
                ldm_x4(bl[j], aB + ARR_BYTES + (uint32_t)(j * 16) * ROWB + ko);
            }
#pragma unroll
            for (int i = 0; i < 4; i++) {
#pragma unroll
                for (int nj = 0; nj < 4; nj++) {
                    const int g = nj >> 1, o = nj & 1;
                    mma16816(acc[i][nj], ah[i], bh[g][o], bh[g][2 + o]);
                    mma16816(acc[i][nj], ah[i], bl[g][o], bl[g][2 + o]);
                    mma16816(acc[i][nj], al[i], bh[g][o], bh[g][2 + o]);
                }
            }
        }
        __syncthreads();
    }

    // Epilogue: thread t owns rows (t/4, t/4+8), cols 2*(t%4) of each tile
    const int tr = lane >> 2, tc = (lane & 3) * 2;
#pragma unroll
    for (int i = 0; i < 4; i++) {
#pragma unroll
        for (int nj = 0; nj < 4; nj++) {
            const int m0 = t0 + wm0 + i * 16 + tr;
            const int n  = o0 + wn0 + nj * 8 + tc;
            float2 v0 = make_float2(acc[i][nj][0], acc[i][nj][1]);
            float2 v1 = make_float2(acc[i][nj][2], acc[i][nj][3]);
            if (HEAD_LAYOUT) {
                size_t base = ((size_t)(n >> 6) * T_DIM) * HD_DIM + (n & 63);
                *(float2*)&C[base + (size_t)m0 * HD_DIM]       = v0;
                *(float2*)&C[base + (size_t)(m0 + 8) * HD_DIM] = v1;
            } else {
                *(float2*)&C[(size_t)m0 * D_DIM + n]       = v0;
                *(float2*)&C[(size_t)(m0 + 8) * D_DIM + n] = v1;
            }
        }
    }
}

// ---------------------------------------------------------------------------
// RoPE, in place on g_Q / g_K
// ---------------------------------------------------------------------------
__global__ __launch_bounds__(256) void rope_kernel()
{
    int idx = blockIdx.x * 256 + threadIdx.x;
    int i = idx & 31;
    int t = (idx >> 5) & (T_DIM - 1);
    int h = idx >> 16;

    float f = exp2f(-(float)i * 0.41524101186092030f);
    float ang = (float)t * f;
    float c = cosf(ang), s = sinf(ang);

    size_t base = ((size_t)h * T_DIM + t) * HD_DIM + i;
    float q1 = g_Q[base], q2 = g_Q[base + 32];
    g_Q[base]      = q1 * c - q2 * s;
    g_Q[base + 32] = q2 * c + q1 * s;
    float k1 = g_K[base], k2 = g_K[base + 32];
    g_K[base]      = k1 * c - k2 * s;
    g_K[base + 32] = k2 * c + k1 * s;
}

// ---------------------------------------------------------------------------
// Flash-style causal attention (unchanged, passing)
// ---------------------------------------------------------------------------
__global__ __launch_bounds__(256) void attn_kernel(
    const float* __restrict__ bias, const float* __restrict__ modw,
    const float* __restrict__ temps)
{
    __shared__ float Qs[64 * 64];
    __shared__ float KP[64 * 64];
    __shared__ float Vs[64 * 64];

    const int tid = threadIdx.x;
    const int tx = tid & 15, ty = tid >> 4;
    const int qb = gridDim.x - 1 - blockIdx.x;
    const int h  = blockIdx.y;
    const int q0 = qb * 64;

    const float sc  = 0.125f * temps[h];
    const float wgt = modw[c_h2m[h]];

    const float* Qg = g_Q + ((size_t)h * T_DIM + q0) * HD_DIM;
    const float* Kg = g_K + (size_t)h * T_DIM * HD_DIM;
    const float* Vg = g_V + (size_t)h * T_DIM * HD_DIM;

    const int lr = tid >> 4;
    const int lc = (tid & 15) << 2;

#pragma unroll
    for (int it = 0; it < 4; it++) {
        int r = lr + it * 16;
        float4 v = *(const float4*)&Qg[r * HD_DIM + lc];
        Qs[(lc + 0) * 64 + r] = v.x; Qs[(lc + 1) * 64 + r] = v.y;
        Qs[(lc + 2) * 64 + r] = v.z; Qs[(lc + 3) * 64 + r] = v.w;
    }

    float m[4], l[4], o[4][4];
#pragma unroll
    for (int i = 0; i < 4; i++) {
        m[i] = -INFINITY; l[i] = 0.f;
#pragma unroll
        for (int j = 0; j < 4; j++) o[i][j] = 0.f;
    }

    for (int kb = 0; kb <= qb; kb++) {
        const int k0 = kb * 64;
        __syncthreads();
#pragma unroll
        for (int it = 0; it < 4; it++) {
            int r = lr + it * 16;
            float4 kv = *(const float4*)&Kg[(size_t)(k0 + r) * HD_DIM + lc];
            KP[(lc + 0) * 64 + r] = kv.x; KP[(lc + 1) * 64 + r] = kv.y;
            KP[(lc + 2) * 64 + r] = kv.z; KP[(lc + 3) * 64 + r] = kv.w;
            float4 vv = *(const float4*)&Vg[(size_t)(k0 + r) * HD_DIM + lc];
            *(float4*)&Vs[r * 64 + lc] = vv;
        }
        __syncthreads();

        float s[4][4];
#pragma unroll
        for (int i = 0; i < 4; i++)
#pragma unroll
            for (int j = 0; j < 4; j++) s[i][j] = 0.f;
#pragma unroll 8
        for (int hd = 0; hd < 64; hd++) {
            float4 qv = *(const float4*)&Qs[hd * 64 + (ty << 2)];
            float4 kv = *(const float4*)&KP[hd * 64 + (tx << 2)];
            s[0][0] += qv.x * kv.x; s[0][1] += qv.x * kv.y;
            s[0][2] += qv.x * kv.z; s[0][3] += qv.x * kv.w;
            s[1][0] += qv.y * kv.x; s[1][1] += qv.y * kv.y;
            s[1][2] += qv.y * kv.z; s[1][3] += qv.y * kv.w;
            s[2][0] += qv.z * kv.x; s[2][1] += qv.z * kv.y;
            s[2][2] += qv.z * kv.z; s[2][3] += qv.z * kv.w;
            s[3][0] += qv.w * kv.x; s[3][1] += qv.w * kv.y;
            s[3][2] += qv.w * kv.z; s[3][3] += qv.w * kv.w;
        }

#pragma unroll
        for (int i = 0; i < 4; i++) {
            int q = q0 + (ty << 2) + i;
            float4 bv = *(const float4*)&bias[(size_t)q * T_DIM + k0 + (tx << 2)];
            float bb[4] = {bv.x, bv.y, bv.z, bv.w};
#pragma unroll
            for (int j = 0; j < 4; j++) {
                int k = k0 + (tx << 2) + j;
                float v = (s[i][j] * sc + bb[j]) * wgt;
                s[i][j] = (k > q) ? -1e30f : v;
            }
        }

        float p[4][4], alpha[4];
#pragma unroll
        for (int i = 0; i < 4; i++) {
            float rm = fmaxf(fmaxf(s[i][0], s[i][1]), fmaxf(s[i][2], s[i][3]));
#pragma unroll
            for (int off = 8; off >= 1; off >>= 1)
                rm = fmaxf(rm, __shfl_xor_sync(0xffffffffu, rm, off));
            float mn = fmaxf(m[i], rm);
            alpha[i] = expf(m[i] - mn);
            m[i] = mn;
            float rs = 0.f;
#pragma unroll
            for (int j = 0; j < 4; j++) { p[i][j] = expf(s[i][j] - mn); rs += p[i][j]; }
#pragma unroll
            for (int off = 8; off >= 1; off >>= 1)
                rs += __shfl_xor_sync(0xffffffffu, rs, off);
            l[i] = l[i] * alpha[i] + rs;
#pragma unroll
            for (int j = 0; j < 4; j++) o[i][j] *= alpha[i];
        }

        __syncthreads();
#pragma unroll
        for (int j = 0; j < 4; j++) {
            float4 pv = make_float4(p[0][j], p[1][j], p[2][j], p[3][j]);
            *(float4*)&KP[((tx << 2) + j) * 64 + (ty << 2)] = pv;
        }
        __syncthreads();

#pragma unroll 8
        for (int kk = 0; kk < 64; kk++) {
            float4 pv = *(const float4*)&KP[kk * 64 + (ty << 2)];
            float4 vv = *(const float4*)&Vs[kk * 64 + (tx << 2)];
            o[0][0] += pv.x * vv.x; o[0][1] += pv.x * vv.y;
            o[0][2] += pv.x * vv.z; o[0][3] += pv.x * vv.w;
            o[1][0] += pv.y * vv.x; o[1][1] += pv.y * vv.y;
            o[1][2] += pv.y * vv.z; o[1][3] += pv.y * vv.w;
            o[2][0] += pv.z * vv.x; o[2][1] += pv.z * vv.y;
            o[2][2] += pv.z * vv.z; o[2][3] += pv.z * vv.w;
            o[3][0] += pv.w * vv.x; o[3][1] += pv.w * vv.y;
            o[3][2] += pv.w * vv.z; o[3][3] += pv.w * vv.w;
        }
    }

#pragma unroll
    for (int i = 0; i < 4; i++) {
        int q = q0 + (ty << 2) + i;
        float inv = 1.f / l[i];
        float4 v = make_float4(o[i][0] * inv, o[i][1] * inv,
                               o[i][2] * inv, o[i][3] * inv);
        *(float4*)&g_O[(size_t)q * D_DIM + h * HD_DIM + (tx << 2)] = v;
    }
}

// ---------------------------------------------------------------------------
extern "C" void kernel_launch(void* const* d_in, const int* in_sizes, int n_in,
                              void* d_out, int out_size)
{
    const float* x  = (const float*)d_in[0];
    const float* cb = (const float*)d_in[2];
    const float* mw = (const float*)d_in[3];
    const float* Wq = (const float*)d_in[4];
    const float* Wk = (const float*)d_in[5];
    const float* Wv = (const float*)d_in[6];
    const float* Wo = (const float*)d_in[7];
    const float* ts = (const float*)d_in[8];
    float* out = (float*)d_out;

    float *gQ, *gK, *gV, *gO;
    cudaGetSymbolAddress((void**)&gQ, g_Q);
    cudaGetSymbolAddress((void**)&gK, g_K);
    cudaGetSymbolAddress((void**)&gV, g_V);
    cudaGetSymbolAddress((void**)&gO, g_O);

    __nv_bfloat16 *xh, *xl, *wqh, *wql, *wkh, *wkl, *wvh, *wvl, *woh, *wol, *oh, *ol;
    cudaGetSymbolAddress((void**)&xh,  g_xh);  cudaGetSymbolAddress((void**)&xl,  g_xl);
    cudaGetSymbolAddress((void**)&wqh, g_wqh); cudaGetSymbolAddress((void**)&wql, g_wql);
    cudaGetSymbolAddress((void**)&wkh, g_wkh); cudaGetSymbolAddress((void**)&wkl, g_wkl);
    cudaGetSymbolAddress((void**)&wvh, g_wvh); cudaGetSymbolAddress((void**)&wvl, g_wvl);
    cudaGetSymbolAddress((void**)&woh, g_woh); cudaGetSymbolAddress((void**)&wol, g_wol);
    cudaGetSymbolAddress((void**)&oh,  g_oh);  cudaGetSymbolAddress((void**)&ol,  g_ol);

    cudaFuncSetAttribute(gemm_tc_kernel<true>,
                         cudaFuncAttributeMaxDynamicSharedMemorySize, GEMM_SMEM);
    cudaFuncSetAttribute(gemm_tc_kernel<false>,
                         cudaFuncAttributeMaxDynamicSharedMemorySize, GEMM_SMEM);

    const int n4blocks = (D_DIM * D_DIM / 4) / 256;   // 4096
    split_kernel<<<n4blocks, 256>>>((const float4*)x,  (__nv_bfloat162*)xh,  (__nv_bfloat162*)xl);
    split_kernel<<<n4blocks, 256>>>((const float4*)Wq, (__nv_bfloat162*)wqh, (__nv_bfloat162*)wql);
    split_kernel<<<n4blocks, 256>>>((const float4*)Wk, (__nv_bfloat162*)wkh, (__nv_bfloat162*)wkl);
    split_kernel<<<n4blocks, 256>>>((const float4*)Wv, (__nv_bfloat162*)wvh, (__nv_bfloat162*)wvl);
    split_kernel<<<n4blocks, 256>>>((const float4*)Wo, (__nv_bfloat162*)woh, (__nv_bfloat162*)wol);

    dim3 ggrid(T_DIM / 128, D_DIM / 128);   // (16, 16)
    gemm_tc_kernel<true><<<ggrid, 256, GEMM_SMEM>>>(xh, xl, wqh, wql, gQ);
    gemm_tc_kernel<true><<<ggrid, 256, GEMM_SMEM>>>(xh, xl, wkh, wkl, gK);
    gemm_tc_kernel<true><<<ggrid, 256, GEMM_SMEM>>>(xh, xl, wvh, wvl, gV);

    rope_kernel<<<(H_NUM * T_DIM * 32) / 256, 256>>>();

    attn_kernel<<<dim3(T_DIM / 64, H_NUM), 256>>>(cb, mw, ts);

    split_kernel<<<n4blocks, 256>>>((const float4*)gO, (__nv_bfloat162*)oh, (__nv_bfloat162*)ol);
    gemm_tc_kernel<false><<<ggrid, 256, GEMM_SMEM>>>(oh, ol, woh, wol, out);
}

// round 4
// speedup vs baseline: 2.5132x; 1.5369x over previous
#include <cuda_runtime.h>
#include <cuda_bf16.h>
#include <math.h>
#include <stdint.h>

#define T_DIM 2048
#define D_DIM 2048
#define H_NUM 32
#define HD_DIM 64

// ---------------------------------------------------------------------------
// Scratch (__device__ globals; allocation-free rule)
// ---------------------------------------------------------------------------
__device__ float g_Q[H_NUM * T_DIM * HD_DIM];   // [H][T][64] fp32 (pre-RoPE)
__device__ float g_K[H_NUM * T_DIM * HD_DIM];
__device__ float g_V[H_NUM * T_DIM * HD_DIM];
__device__ float g_O[T_DIM * D_DIM];            // attention output, [T][D]

// bf16 hi/lo splits
__device__ __nv_bfloat16 g_xh[D_DIM * D_DIM],  g_xl[D_DIM * D_DIM];
__device__ __nv_bfloat16 g_wqh[D_DIM * D_DIM], g_wql[D_DIM * D_DIM];
__device__ __nv_bfloat16 g_wkh[D_DIM * D_DIM], g_wkl[D_DIM * D_DIM];
__device__ __nv_bfloat16 g_wvh[D_DIM * D_DIM], g_wvl[D_DIM * D_DIM];
__device__ __nv_bfloat16 g_woh[D_DIM * D_DIM], g_wol[D_DIM * D_DIM];
__device__ __nv_bfloat16 g_oh[D_DIM * D_DIM],  g_ol[D_DIM * D_DIM];
// RoPE'd Q/K and V, bf16 hi/lo, [H][T][64]
__device__ __nv_bfloat16 g_Qh[H_NUM * T_DIM * HD_DIM], g_Ql[H_NUM * T_DIM * HD_DIM];
__device__ __nv_bfloat16 g_Kh[H_NUM * T_DIM * HD_DIM], g_Kl[H_NUM * T_DIM * HD_DIM];
__device__ __nv_bfloat16 g_Vh[H_NUM * T_DIM * HD_DIM], g_Vl[H_NUM * T_DIM * HD_DIM];

// head -> module index, HEAD_COUNTS = {8,6,4,4,6,4}
__constant__ int c_h2m[H_NUM] = {0,0,0,0,0,0,0,0,
                                 1,1,1,1,1,1,
                                 2,2,2,2,
                                 3,3,3,3,
                                 4,4,4,4,4,4,
                                 5,5,5,5};

// ---------------------------------------------------------------------------
// PTX helpers (sm_100-safe: cp.async / ldmatrix / mma.sync)
// ---------------------------------------------------------------------------
__device__ __forceinline__ uint32_t s2u(const void* p) {
    uint32_t a;
    asm("{ .reg .u64 t; cvta.to.shared.u64 t, %1; cvt.u32.u64 %0, t; }"
        : "=r"(a) : "l"(p));
    return a;
}
__device__ __forceinline__ void cp16(uint32_t d, const void* s) {
    asm volatile("cp.async.cg.shared.global [%0], [%1], 16;" :: "r"(d), "l"(s));
}
__device__ __forceinline__ void cp_commit() {
    asm volatile("cp.async.commit_group;" ::: "memory");
}
__device__ __forceinline__ void cp_wait1() {
    asm volatile("cp.async.wait_group 1;" ::: "memory");
}
__device__ __forceinline__ void ldm_x4(uint32_t* r, uint32_t a) {
    asm volatile("ldmatrix.sync.aligned.m8n8.x4.shared.b16 {%0,%1,%2,%3}, [%4];"
                 : "=r"(r[0]), "=r"(r[1]), "=r"(r[2]), "=r"(r[3]) : "r"(a));
}
__device__ __forceinline__ void ldm_x4_t(uint32_t* r, uint32_t a) {
    asm volatile("ldmatrix.sync.aligned.m8n8.x4.trans.shared.b16 {%0,%1,%2,%3}, [%4];"
                 : "=r"(r[0]), "=r"(r[1]), "=r"(r[2]), "=r"(r[3]) : "r"(a));
}
__device__ __forceinline__ void mma16816(float* d, const uint32_t* a,
                                         uint32_t b0, uint32_t b1) {
    asm volatile("mma.sync.aligned.m16n8k16.row.col.f32.bf16.bf16.f32 "
        "{%0,%1,%2,%3},{%4,%5,%6,%7},{%8,%9},{%0,%1,%2,%3};"
        : "+f"(d[0]), "+f"(d[1]), "+f"(d[2]), "+f"(d[3])
        : "r"(a[0]), "r"(a[1]), "r"(a[2]), "r"(a[3]), "r"(b0), "r"(b1));
}
__device__ __forceinline__ float ex2(float x) {
    float r;
    asm("ex2.approx.f32 %0, %1;" : "=f"(r) : "f"(x));
    return r;
}
// pack two f32 -> bf16x2 (lo = a, hi = b)
__device__ __forceinline__ uint32_t pack_bf2(float a, float b) {
    uint32_t r;
    asm("cvt.rn.bf16x2.f32 %0, %1, %2;" : "=r"(r) : "f"(b), "f"(a));
    return r;
}
__device__ __forceinline__ float bf_lo(uint32_t v) { return __uint_as_float(v << 16); }
__device__ __forceinline__ float bf_hi(uint32_t v) { return __uint_as_float(v & 0xFFFF0000u); }

// ---------------------------------------------------------------------------
// fp32 -> bf16 hi/lo split
// ---------------------------------------------------------------------------
__global__ __launch_bounds__(256) void split_kernel(
    const float4* __restrict__ src,
    __nv_bfloat162* __restrict__ hi, __nv_bfloat162* __restrict__ lo)
{
    int i = blockIdx.x * 256 + threadIdx.x;
    float4 v = src[i];
    __nv_bfloat16 h0 = __float2bfloat16(v.x), h1 = __float2bfloat16(v.y);
    __nv_bfloat16 h2 = __float2bfloat16(v.z), h3 = __float2bfloat16(v.w);
    float l0 = v.x - __bfloat162float(h0), l1 = v.y - __bfloat162float(h1);
    float l2 = v.z - __bfloat162float(h2), l3 = v.w - __bfloat162float(h3);
    hi[2 * i]     = __halves2bfloat162(h0, h1);
    hi[2 * i + 1] = __halves2bfloat162(h2, h3);
    lo[2 * i]     = __halves2bfloat162(__float2bfloat16(l0), __float2bfloat16(l1));
    lo[2 * i + 1] = __halves2bfloat162(__float2bfloat16(l2), __float2bfloat16(l3));
}

// ---------------------------------------------------------------------------
// RoPE + hi/lo split for Q,K: read fp32 g_Q/g_K, write bf16 g_Qh/Ql/Kh/Kl
// ---------------------------------------------------------------------------
__global__ __launch_bounds__(256) void rope_split_kernel()
{
    int idx = blockIdx.x * 256 + threadIdx.x;
    int i = idx & 31;
    int t = (idx >> 5) & (T_DIM - 1);
    int h = idx >> 16;

    float f = exp2f(-(float)i * 0.41524101186092030f);   // 10000^(-i/32)
    float ang = (float)t * f;
    float c = cosf(ang), s = sinf(ang);

    size_t base = ((size_t)h * T_DIM + t) * HD_DIM + i;
    float q1 = g_Q[base], q2 = g_Q[base + 32];
    float qa = q1 * c - q2 * s;
    float qb = q2 * c + q1 * s;
    float k1 = g_K[base], k2 = g_K[base + 32];
    float ka = k1 * c - k2 * s;
    float kb = k2 * c + k1 * s;

    __nv_bfloat16 hqa = __float2bfloat16(qa), hqb = __float2bfloat16(qb);
    __nv_bfloat16 hka = __float2bfloat16(ka), hkb = __float2bfloat16(kb);
    g_Qh[base]      = hqa; g_Ql[base]      = __float2bfloat16(qa - __bfloat162float(hqa));
    g_Qh[base + 32] = hqb; g_Ql[base + 32] = __float2bfloat16(qb - __bfloat162float(hqb));
    g_Kh[base]      = hka; g_Kl[base]      = __float2bfloat16(ka - __bfloat162float(hka));
    g_Kh[base + 32] = hkb; g_Kl[base + 32] = __float2bfloat16(kb - __bfloat162float(hkb));
}

// ---------------------------------------------------------------------------
// Dense GEMM C = A * W^T (unchanged from round 3, passing)
// ---------------------------------------------------------------------------
#define ROWB      80
#define ARR_BYTES (128 * ROWB)
#define STG_BYTES (4 * ARR_BYTES)
#define N_STAGE   3
#define GEMM_SMEM (N_STAGE * STG_BYTES)

__device__ __forceinline__ void g_load_stage(
    uint32_t st, const __nv_bfloat16* __restrict__ Ah, const __nv_bfloat16* __restrict__ Al,
    const __nv_bfloat16* __restrict__ Bh, const __nv_bfloat16* __restrict__ Bl,
    int t0, int o0, int k0, int tid)
{
    const int r = tid >> 2;
    const int c = (tid & 3);
    const int e = c * 8;
#pragma unroll
    for (int half = 0; half < 2; half++) {
        int row = r + half * 64;
        uint32_t so = row * ROWB + c * 16;
        size_t ga = (size_t)(t0 + row) * D_DIM + k0 + e;
        size_t gb = (size_t)(o0 + row) * D_DIM + k0 + e;
        cp16(st + so,                 Ah + ga);
        cp16(st + ARR_BYTES + so,     Al + ga);
        cp16(st + 2 * ARR_BYTES + so, Bh + gb);
        cp16(st + 3 * ARR_BYTES + so, Bl + gb);
    }
    cp_commit();
}

template<bool HEAD_LAYOUT>
__global__ __launch_bounds__(256, 1) void gemm_tc_kernel(
    const __nv_bfloat16* __restrict__ Ah, const __nv_bfloat16* __restrict__ Al,
    const __nv_bfloat16* __restrict__ Bh, const __nv_bfloat16* __restrict__ Bl,
    float* __restrict__ C)
{
    extern __shared__ char smem[];
    const uint32_t sb = s2u(smem);
    const int tid  = threadIdx.x;
    const int w    = tid >> 5;
    const int lane = tid & 31;
    const int t0 = blockIdx.x * 128;
    const int o0 = blockIdx.y * 128;
    const int wm0 = (w >> 2) * 64;
    const int wn0 = (w & 3) * 32;

    float acc[4][4][4];
#pragma unroll
    for (int i = 0; i < 4; i++)
#pragma unroll
        for (int j = 0; j < 4; j++)
#pragma unroll
            for (int q = 0; q < 4; q++) acc[i][j][q] = 0.f;

    g_load_stage(sb,             Ah, Al, Bh, Bl, t0, o0, 0,  tid);
    g_load_stage(sb + STG_BYTES, Ah, Al, Bh, Bl, t0, o0, 32, tid);

    const int lm = lane & 15;
    const uint32_t kb = (uint32_t)(lane >> 4) * 16;

    for (int it = 0; it < 64; it++) {
        cp_wait1();
        __syncthreads();
        if (it < 62)
            g_load_stage(sb + (uint32_t)((it + 2) % N_STAGE) * STG_BYTES,
                         Ah, Al, Bh, Bl, t0, o0, (it + 2) * 32, tid);
        else
            cp_commit();

        const uint32_t st = sb + (uint32_t)(it % N_STAGE) * STG_BYTES;
        const uint32_t aA = st + (uint32_t)(wm0 + lm) * ROWB + kb;
        const uint32_t aB = st + 2u * ARR_BYTES + (uint32_t)(wn0 + lm) * ROWB + kb;

#pragma unroll
        for (int ks = 0; ks < 2; ks++) {
            const uint32_t ko = (uint32_t)ks * 32;
            uint32_t ah[4][4], al[4][4], bh[2][4], bl[2][4];
#pragma unroll
            for (int i = 0; i < 4; i++) {
                ldm_x4(ah[i], aA + (uint32_t)(i * 16) * ROWB + ko);
                ldm_x4(al[i], aA + ARR_BYTES + (uint32_t)(i * 16) * ROWB + ko);
            }
#pragma unroll
            for (int j = 0; j < 2; j++) {
                ldm_x4(bh[j], aB + (uint32_t)(j * 16) * ROWB + ko);
                ldm_x4(bl[j], aB + ARR_BYTES + (uint32_t)(j * 16) * ROWB + ko);
            }
#pragma unroll
            for (int i = 0; i < 4; i++) {
#pragma unroll
                for (int nj = 0; nj < 4; nj++) {
                    const int g = nj >> 1, o = nj & 1;
                    mma16816(acc[i][nj], ah[i], bh[g][o], bh[g][2 + o]);
                    mma16816(acc[i][nj], ah[i], bl[g][o], bl[g][2 + o]);
                    mma16816(acc[i][nj], al[i], bh[g][o], bh[g][2 + o]);
                }
            }
        }
        __syncthreads();
    }

    const int tr = lane >> 2, tc = (lane & 3) * 2;
#pragma unroll
    for (int i = 0; i < 4; i++) {
#pragma unroll
        for (int nj = 0; nj < 4; nj++) {
            const int m0 = t0 + wm0 + i * 16 + tr;
            const int n  = o0 + wn0 + nj * 8 + tc;
            float2 v0 = make_float2(acc[i][nj][0], acc[i][nj][1]);
            float2 v1 = make_float2(acc[i][nj][2], acc[i][nj][3]);
            if (HEAD_LAYOUT) {
                size_t base = ((size_t)(n >> 6) * T_DIM) * HD_DIM + (n & 63);
                *(float2*)&C[base + (size_t)m0 * HD_DIM]       = v0;
                *(float2*)&C[base + (size_t)(m0 + 8) * HD_DIM] = v1;
            } else {
                *(float2*)&C[(size_t)m0 * D_DIM + n]       = v0;
                *(float2*)&C[(size_t)(m0 + 8) * D_DIM + n] = v1;
            }
        }
    }
}

// ---------------------------------------------------------------------------
// Tensor-core flash attention, bf16 hi/lo.
// CTA = (128 q-rows, 1 head); 8 warps x 16 rows; k-tiles of 128, double-buffered.
// Smem rows: 64 bf16 = 128B, padded to 144B (conflict-free ldmatrix).
// ---------------------------------------------------------------------------
#define AROWB 144
#define ATILE (128 * AROWB)                 // 18432 B per [128 x 64]bf16 array
#define ATT_SMEM (2 * ATILE + 2 * 4 * ATILE)  // Qh,Ql + 2 stages of (Kh,Kl,Vh,Vl)
#define LOG2E 1.4426950408889634f

__device__ __forceinline__ void a_load_stage(
    uint32_t st, const __nv_bfloat16* __restrict__ Kh, const __nv_bfloat16* __restrict__ Kl,
    const __nv_bfloat16* __restrict__ Vh, const __nv_bfloat16* __restrict__ Vl,
    int k0, int tid)
{
#pragma unroll
    for (int i = 0; i < 4; i++) {
        int q = tid + i * 256;
        int row = q >> 3, cc = q & 7;
        uint32_t so = row * AROWB + cc * 16;
        size_t g = (size_t)(k0 + row) * HD_DIM + cc * 8;
        cp16(st + so,             Kh + g);
        cp16(st + ATILE + so,     Kl + g);
        cp16(st + 2 * ATILE + so, Vh + g);
        cp16(st + 3 * ATILE + so, Vl + g);
    }
}

__global__ __launch_bounds__(256, 1) void attn_tc_kernel(
    const float* __restrict__ bias, const float* __restrict__ modw,
    const float* __restrict__ temps)
{
    extern __shared__ char smem[];
    const uint32_t sb = s2u(smem);
    const uint32_t sQh = sb, sQl = sb + ATILE;
    const uint32_t sStage = sb + 2 * ATILE;

    const int tid  = threadIdx.x;
    const int w    = tid >> 5;
    const int lane = tid & 31;
    const int qb = gridDim.x - 1 - blockIdx.x;   // heavy tiles first
    const int h  = blockIdx.y;
    const int q0 = qb * 128;

    const float wgt = modw[c_h2m[h]];
    const float A1  = 0.125f * temps[h] * wgt * LOG2E;  // logit = s*sc*wgt + bias*wgt (log2 dom)
    const float B1  = wgt * LOG2E;

    const __nv_bfloat16* Qhg = g_Qh + ((size_t)h * T_DIM + q0) * HD_DIM;
    const __nv_bfloat16* Qlg = g_Ql + ((size_t)h * T_DIM + q0) * HD_DIM;
    const __nv_bfloat16* Khg = g_Kh + (size_t)h * T_DIM * HD_DIM;
    const __nv_bfloat16* Klg = g_Kl + (size_t)h * T_DIM * HD_DIM;
    const __nv_bfloat16* Vhg = g_Vh + (size_t)h * T_DIM * HD_DIM;
    const __nv_bfloat16* Vlg = g_Vl + (size_t)h * T_DIM * HD_DIM;

    // Prologue: group0 = Q + stage0 ; group1 = stage1 (possibly empty)
#pragma unroll
    for (int i = 0; i < 4; i++) {
        int q = tid + i * 256;
        int row = q >> 3, cc = q & 7;
        uint32_t so = row * AROWB + cc * 16;
        size_t g = (size_t)row * HD_DIM + cc * 8;
        cp16(sQh + so, Qhg + g);
        cp16(sQl + so, Qlg + g);
    }
    a_load_stage(sStage, Khg, Klg, Vhg, Vlg, 0, tid);
    cp_commit();
    if (qb >= 1) a_load_stage(sStage + 4 * ATILE, Khg, Klg, Vhg, Vlg, 128, tid);
    cp_commit();

    const int wq  = w * 16;            // warp's q-row offset in tile
    const int lm  = lane & 15;
    const uint32_t kboff = (uint32_t)(lane >> 4) * 16;   // A/B frag 16B col offset
    const int r   = lane >> 2;
    const int c2  = (lane & 3) * 2;
    const int qr0 = q0 + wq + r;       // global q rows owned by this lane
    const int qr1 = qr0 + 8;

    float m0 = -1e30f, m1 = -1e30f, l0 = 0.f, l1 = 0.f;
    float o[8][4];
#pragma unroll
    for (int j = 0; j < 8; j++)
#pragma unroll
        for (int q = 0; q < 4; q++) o[j][q] = 0.f;

    const uint32_t aQh = sQh + (uint32_t)(wq + lm) * AROWB + kboff;
    const uint32_t aQl = sQl + (uint32_t)(wq + lm) * AROWB + kboff;

    for (int kb = 0; kb <= qb; kb++) {
        cp_wait1();
        __syncthreads();
        const uint32_t st = sStage + (uint32_t)(kb & 1) * 4 * ATILE;
        const bool diag = (kb == qb);
        const int k0 = kb * 128;

        // ---- S = Q K^T (hi/lo, 3 passes) ----
        float s[16][4];
#pragma unroll
        for (int j = 0; j < 16; j++)
#pragma unroll
            for (int q = 0; q < 4; q++) s[j][q] = 0.f;

#pragma unroll
        for (int ks = 0; ks < 4; ks++) {
            const uint32_t ko = (uint32_t)ks * 32;
            uint32_t ah[4], al[4];
            ldm_x4(ah, aQh + ko);
            ldm_x4(al, aQl + ko);
#pragma unroll
            for (int ng = 0; ng < 8; ng++) {
                uint32_t bh[4], bl[4];
                const uint32_t aK = st + (uint32_t)(ng * 16 + lm) * AROWB + kboff + ko;
                ldm_x4(bh, aK);
                ldm_x4(bl, aK + ATILE);
                mma16816(s[2 * ng],     ah, bh[0], bh[2]);
                mma16816(s[2 * ng + 1], ah, bh[1], bh[3]);
                mma16816(s[2 * ng],     ah, bl[0], bl[2]);
                mma16816(s[2 * ng + 1], ah, bl[1], bl[3]);
                mma16816(s[2 * ng],     al, bh[0], bh[2]);
                mma16816(s[2 * ng + 1], al, bh[1], bh[3]);
            }
        }

        // ---- bias + scale + mask (log2 domain) ----
        const float* br0 = bias + (size_t)qr0 * T_DIM + k0;
        const float* br1 = bias + (size_t)qr1 * T_DIM + k0;
        float vmax0 = -1e30f, vmax1 = -1e30f;
#pragma unroll
        for (int j = 0; j < 16; j++) {
            const int kc = j * 8 + c2;
            float2 b0 = *(const float2*)(br0 + kc);
            float2 b1 = *(const float2*)(br1 + kc);
            s[j][0] = s[j][0] * A1 + b0.x * B1;
            s[j][1] = s[j][1] * A1 + b0.y * B1;
            s[j][2] = s[j][2] * A1 + b1.x * B1;
            s[j][3] = s[j][3] * A1 + b1.y * B1;
            if (diag) {
                const int ka = k0 + kc;
                if (ka > qr0)     s[j][0] = -1e30f;
                if (ka + 1 > qr0) s[j][1] = -1e30f;
                if (ka > qr1)     s[j][2] = -1e30f;
                if (ka + 1 > qr1) s[j][3] = -1e30f;
            }
            vmax0 = fmaxf(vmax0, fmaxf(s[j][0], s[j][1]));
            vmax1 = fmaxf(vmax1, fmaxf(s[j][2], s[j][3]));
        }
        vmax0 = fmaxf(vmax0, __shfl_xor_sync(0xffffffffu, vmax0, 1));
        vmax0 = fmaxf(vmax0, __shfl_xor_sync(0xffffffffu, vmax0, 2));
        vmax1 = fmaxf(vmax1, __shfl_xor_sync(0xffffffffu, vmax1, 1));
        vmax1 = fmaxf(vmax1, __shfl_xor_sync(0xffffffffu, vmax1, 2));

        const float mn0 = fmaxf(m0, vmax0);
        const float mn1 = fmaxf(m1, vmax1);
        const float al0 = ex2(m0 - mn0);
        const float al1 = ex2(m1 - mn1);
        m0 = mn0; m1 = mn1;

        float rs0 = 0.f, rs1 = 0.f;
#pragma unroll
        for (int j = 0; j < 16; j++) {
            s[j][0] = ex2(s[j][0] - mn0);
            s[j][1] = ex2(s[j][1] - mn0);
            s[j][2] = ex2(s[j][2] - mn1);
            s[j][3] = ex2(s[j][3] - mn1);
            rs0 += s[j][0] + s[j][1];
            rs1 += s[j][2] + s[j][3];
        }
        rs0 += __shfl_xor_sync(0xffffffffu, rs0, 1);
        rs0 += __shfl_xor_sync(0xffffffffu, rs0, 2);
        rs1 += __shfl_xor_sync(0xffffffffu, rs1, 1);
        rs1 += __shfl_xor_sync(0xffffffffu, rs1, 2);
        l0 = l0 * al0 + rs0;
        l1 = l1 * al1 + rs1;

#pragma unroll
        for (int j = 0; j < 8; j++) {
            o[j][0] *= al0; o[j][1] *= al0;
            o[j][2] *= al1; o[j][3] *= al1;
        }

        // ---- O += P V (hi/lo, 3 passes) ----
#pragma unroll
        for (int ks = 0; ks < 8; ks++) {
            uint32_t ph[4], pl[4];
#pragma unroll
            for (int u = 0; u < 2; u++) {           // tiles 2ks, 2ks+1
                const int j = 2 * ks + u;
                uint32_t d0 = pack_bf2(s[j][0], s[j][1]);
                uint32_t d1 = pack_bf2(s[j][2], s[j][3]);
                ph[u]     = d0;  ph[2 + u] = d1;
                pl[u]     = pack_bf2(s[j][0] - bf_lo(d0), s[j][1] - bf_hi(d0));
                pl[2 + u] = pack_bf2(s[j][2] - bf_lo(d1), s[j][3] - bf_hi(d1));
            }
            // A frag order: a0=(r,k0k1) a1=(r+8,k0k1) a2=(r,k8k9) a3=(r+8,k8k9)
            uint32_t pa_h[4] = { ph[0], ph[2], ph[1], ph[3] };
            uint32_t pa_l[4] = { pl[0], pl[2], pl[1], pl[3] };
#pragma unroll
            for (int nv = 0; nv < 2; nv++) {        // d in 2 x n32 via 2 x (n16 trans ldm)
#pragma unroll
                for (int half = 0; half < 2; half++) {
                    const int n0 = nv * 32 + half * 16;
                    const uint32_t aV = st + 2 * ATILE
                        + (uint32_t)(ks * 16 + lm) * AROWB
                        + (uint32_t)(n0 + ((lane >> 4) * 8)) * 2;
                    uint32_t vh[4], vl[4];
                    ldm_x4_t(vh, aV);
                    ldm_x4_t(vl, aV + ATILE);
                    const int jt = nv * 4 + half * 2;
                    mma16816(o[jt],     pa_h, vh[0], vh[1]);
                    mma16816(o[jt + 1], pa_h, vh[2], vh[3]);
                    mma16816(o[jt],     pa_h, vl[0], vl[1]);
                    mma16816(o[jt + 1], pa_h, vl[2], vl[3]);
                    mma16816(o[jt],     pa_l, vh[0], vh[1]);
                    mma16816(o[jt + 1], pa_l, vh[2], vh[3]);
                }
            }
        }

        __syncthreads();   // done reading stage kb
        if (kb + 2 <= qb)
            a_load_stage(sStage + (uint32_t)(kb & 1) * 4 * ATILE,
                         Khg, Klg, Vhg, Vlg, (kb + 2) * 128, tid);
        cp_commit();
    }

    // ---- epilogue: normalize, write [T][D] ----
    const float inv0 = 1.f / l0, inv1 = 1.f / l1;
#pragma unroll
    for (int j = 0; j < 8; j++) {
        const int d = j * 8 + c2;
        *(float2*)&g_O[(size_t)qr0 * D_DIM + h * HD_DIM + d] =
            make_float2(o[j][0] * inv0, o[j][1] * inv0);
        *(float2*)&g_O[(size_t)qr1 * D_DIM + h * HD_DIM + d] =
            make_float2(o[j][2] * inv1, o[j][3] * inv1);
    }
}

// ---------------------------------------------------------------------------
extern "C" void kernel_launch(void* const* d_in, const int* in_sizes, int n_in,
                              void* d_out, int out_size)
{
    const float* x  = (const float*)d_in[0];
    const float* cb = (const float*)d_in[2];
    const float* mw = (const float*)d_in[3];
    const float* Wq = (const float*)d_in[4];
    const float* Wk = (const float*)d_in[5];
    const float* Wv = (const float*)d_in[6];
    const float* Wo = (const float*)d_in[7];
    const float* ts = (const float*)d_in[8];
    float* out = (float*)d_out;

    float *gQ, *gK, *gV, *gO;
    cudaGetSymbolAddress((void**)&gQ, g_Q);
    cudaGetSymbolAddress((void**)&gK, g_K);
    cudaGetSymbolAddress((void**)&gV, g_V);
    cudaGetSymbolAddress((void**)&gO, g_O);

    __nv_bfloat16 *xh, *xl, *wqh, *wql, *wkh, *wkl, *wvh, *wvl, *woh, *wol, *oh, *ol;
    __nv_bfloat16 *vh, *vl;
    cudaGetSymbolAddress((void**)&xh,  g_xh);  cudaGetSymbolAddress((void**)&xl,  g_xl);
    cudaGetSymbolAddress((void**)&wqh, g_wqh); cudaGetSymbolAddress((void**)&wql, g_wql);
    cudaGetSymbolAddress((void**)&wkh, g_wkh); cudaGetSymbolAddress((void**)&wkl, g_wkl);
    cudaGetSymbolAddress((void**)&wvh, g_wvh); cudaGetSymbolAddress((void**)&wvl, g_wvl);
    cudaGetSymbolAddress((void**)&woh, g_woh); cudaGetSymbolAddress((void**)&wol, g_wol);
    cudaGetSymbolAddress((void**)&oh,  g_oh);  cudaGetSymbolAddress((void**)&ol,  g_ol);
    cudaGetSymbolAddress((void**)&vh,  g_Vh);  cudaGetSymbolAddress((void**)&vl,  g_Vl);

    cudaFuncSetAttribute(gemm_tc_kernel<true>,
                         cudaFuncAttributeMaxDynamicSharedMemorySize, GEMM_SMEM);
    cudaFuncSetAttribute(gemm_tc_kernel<false>,
                         cudaFuncAttributeMaxDynamicSharedMemorySize, GEMM_SMEM);
    cudaFuncSetAttribute(attn_tc_kernel,
                         cudaFuncAttributeMaxDynamicSharedMemorySize, ATT_SMEM);

    const int n4blocks = (D_DIM * D_DIM / 4) / 256;   // 4096
    split_kernel<<<n4blocks, 256>>>((const float4*)x,  (__nv_bfloat162*)xh,  (__nv_bfloat162*)xl);
    split_kernel<<<n4blocks, 256>>>((const float4*)Wq, (__nv_bfloat162*)wqh, (__nv_bfloat162*)wql);
    split_kernel<<<n4blocks, 256>>>((const float4*)Wk, (__nv_bfloat162*)wkh, (__nv_bfloat162*)wkl);
    split_kernel<<<n4blocks, 256>>>((const float4*)Wv, (__nv_bfloat162*)wvh, (__nv_bfloat162*)wvl);
    split_kernel<<<n4blocks, 256>>>((const float4*)Wo, (__nv_bfloat162*)woh, (__nv_bfloat162*)wol);

    dim3 ggrid(T_DIM / 128, D_DIM / 128);   // (16, 16)
    gemm_tc_kernel<true><<<ggrid, 256, GEMM_SMEM>>>(xh, xl, wqh, wql, gQ);
    gemm_tc_kernel<true><<<ggrid, 256, GEMM_SMEM>>>(xh, xl, wkh, wkl, gK);
    gemm_tc_kernel<true><<<ggrid, 256, GEMM_SMEM>>>(xh, xl, wvh, wvl, gV);

    rope_split_kernel<<<(H_NUM * T_DIM * 32) / 256, 256>>>();
    split_kernel<<<n4blocks, 256>>>((const float4*)gV, (__nv_bfloat162*)vh, (__nv_bfloat162*)vl);

    attn_tc_kernel<<<dim3(T_DIM / 128, H_NUM), 256, ATT_SMEM>>>(cb, mw, ts);

    split_kernel<<<n4blocks, 256>>>((const float4*)gO, (__nv_bfloat162*)oh, (__nv_bfloat162*)ol);
    gemm_tc_kernel<false><<<ggrid, 256, GEMM_SMEM>>>(oh, ol, woh, wol, out);
}